// round 13
// baseline (speedup 1.0000x reference)
#include <cuda_runtime.h>
#include <cuda_fp16.h>
#include <cstdint>

// ---------------------------------------------------------------------------
// EvalNet: EmbeddingBag(sum,pad) -> screlu -> fc2(1024->32) -> screlu
//          -> bucketed cp/wdl heads.   (sm_100 SIMT)
// P : emb fp32->fp16 (769 blocks); w transpose g_wT[c*32+j] (64 blocks).
// K1: 64-col chunked gather (2 CTAs/SM!), 64-sample tiles, depth-2 HADD2
//     tree; h PAIR-INTERLEAVED fp32.
// K2: R12 triple-buffered cp.async pipeline (frozen).
// ---------------------------------------------------------------------------

#define HIDDEN   1024
#define NROWS    769
#define MAX_B    16384

#define CHUNK1   64
#define NCHUNKS1 (HIDDEN / CHUNK1)   // 16
#define NGROUPS1 18                  // 16*18 = 288 blocks, 2/SM resident
#define K1T      512
#define TILE1    64

#define K2T      256
#define TS2      64                  // samples per K2 block (grid 256)
#define CHUNK2   64
#define NCH2     (HIDDEN / CHUNK2)   // 16

__device__ float  g_h[(size_t)MAX_B * HIDDEN];   // pair-interleaved hidden
__device__ __half g_emb_h[NROWS * HIDDEN];       // fp16 table
__device__ float  g_wT[HIDDEN * 32];             // wT[c*32+j] = fc2_w[j][c]

__device__ __forceinline__ float screlu1(float v)
{
    float c = fminf(fmaxf(v, 0.0f), 1.0f);
    return c * c;
}

__device__ __forceinline__ void fma2(unsigned long long& acc,
                                     unsigned long long a,
                                     unsigned long long b)
{
    asm("fma.rn.f32x2 %0, %1, %2, %0;" : "+l"(acc) : "l"(a), "l"(b));
}

__device__ __forceinline__ void add2(unsigned long long& acc,
                                     unsigned long long v)
{
    asm("add.rn.f32x2 %0, %0, %1;" : "+l"(acc) : "l"(v));
}

__device__ __forceinline__ unsigned long long packdup(float w)
{
    unsigned long long r;
    asm("mov.b64 %0, {%1, %1};" : "=l"(r) : "f"(w));
    return r;
}

__device__ __forceinline__ uint32_t smem_u32(const void* p)
{
    uint32_t a;
    asm("{ .reg .u64 t; cvta.to.shared.u64 t, %1; cvt.u32.u64 %0, t; }"
        : "=r"(a) : "l"(p));
    return a;
}

__device__ __forceinline__ void cp_async16(uint32_t dst, const void* src)
{
    asm volatile("cp.async.ca.shared.global [%0], [%1], 16;"
                 :: "r"(dst), "l"(__cvta_generic_to_global(src)));
}

#define CP_COMMIT() asm volatile("cp.async.commit_group;" ::: "memory")
#define CP_WAIT0()  asm volatile("cp.async.wait_group 0;" ::: "memory")
#define CP_WAIT1()  asm volatile("cp.async.wait_group 1;" ::: "memory")

union F2U { float2 f; unsigned long long u; };

#define H2(u) (*(const __half2*)&(u))

// ---------------------------------------------------------------------------
// P: blocks 0..768: emb row -> fp16; blocks 769..832: wT build.
// ---------------------------------------------------------------------------
__global__ __launch_bounds__(512)
void prep_kernel(const float* __restrict__ emb,
                 const float* __restrict__ fc2_w)
{
    const int b = blockIdx.x, tid = threadIdx.x;
    if (b < NROWS) {
        const float2* src = (const float2*)(emb + b * HIDDEN);
        __half2* dst = (__half2*)(g_emb_h + b * HIDDEN);
        dst[tid] = __floats2half2_rn(src[tid].x, src[tid].y);
    } else {
        int i = (b - NROWS) * 512 + tid;
        int j = i >> 10, c = i & 1023;
        g_wT[c * 32 + j] = fc2_w[i];
    }
}

// ---------------------------------------------------------------------------
// K1: gather + bias + screlu over a 64-col fp16 table slice; 2 CTAs/SM.
// Thread (s = tid>>3, q = tid&7) owns cols 8q..8q+7 of sample s in the
// 64-sample tile. Partner for pair-interleave = s^1 = lane^8.
// smem: tab 96KB (row stride 8 uint4) + idx 2x2048 ints + bias + nz.
// ---------------------------------------------------------------------------
#define K1_TAB_BYTES (NROWS * CHUNK1 * 2)        // 98432
#define K1_IDX_OFF   K1_TAB_BYTES
#define K1_BIAS_OFF  (K1_IDX_OFF + 2 * TILE1 * 32 * 4)
#define K1_NZ_OFF    (K1_BIAS_OFF + CHUNK1 * 4)
#define K1_SMEM      (K1_NZ_OFF + 16)

__global__ __launch_bounds__(K1T, 2)
void gather_kernel(const void* __restrict__ xv,
                   const float* __restrict__ bias1,
                   int B)
{
    extern __shared__ char smem[];
    __half* s_tab  = (__half*)smem;
    int*    s_idx  = (int*)(smem + K1_IDX_OFF);
    float*  s_bias = (float*)(smem + K1_BIAS_OFF);
    int*    s_nz   = (int*)(smem + K1_NZ_OFF);

    const int tid   = threadIdx.x;
    const int cbase = blockIdx.x * CHUNK1;

    if (tid == 0) *s_nz = 0;
    __syncthreads();

    if (tid < 64) {
        if (((const unsigned int*)xv)[2 * tid + 1]) atomicOr(s_nz, 1);
    }

    // Stage the fp16 table slice: 769 rows x 64 cols = 8 uint4 per row.
    {
        const uint4* src = (const uint4*)g_emb_h;     // row stride 128 uint4
        uint4*       dst = (uint4*)s_tab;             // row stride 8 uint4
        const int cb8 = cbase >> 3;
        for (int i = tid; i < NROWS * 8; i += K1T) {
            int row = i >> 3, u = i & 7;
            dst[i] = src[row * 128 + cb8 + u];
        }
    }
    if (tid < CHUNK1) s_bias[tid] = bias1[cbase + tid];
    __syncthreads();

    const int is64 = (*s_nz == 0);

    const int s   = tid >> 3;     // sample within 64-tile
    const int q   = tid & 7;      // 16B column group (8 halves)
    const int odd = s & 1;

    const int spg     = (((B + NGROUPS1 - 1) / NGROUPS1) + TILE1 - 1) & ~(TILE1 - 1);
    const int s_begin = blockIdx.y * spg;
    const int s_end   = min(B, s_begin + spg);

    const int*       x32 = (const int*)xv;
    const long long* x64 = (const long long*)xv;
    float2*          ghp = (float2*)g_h;
    const uint4*     tab4 = (const uint4*)s_tab;

    // preload first tile's indices into registers (4 per thread; 2048/tile)
    int pre[4] = {NROWS - 1, NROWS - 1, NROWS - 1, NROWS - 1};
    if (s_begin < s_end) {
        #pragma unroll
        for (int k = 0; k < 4; k++) {
            int j = tid + k * K1T;
            int samp = s_begin + (j >> 5);
            int v = NROWS - 1;
            if (samp < B) {
                int r = j & 31;
                v = is64 ? (int)x64[(size_t)samp * 32 + r]
                         : x32[samp * 32 + r];
            }
            pre[k] = v;
        }
    }

    int buf = 0;
    for (int t0 = s_begin; t0 < s_end; t0 += TILE1) {
        #pragma unroll
        for (int k = 0; k < 4; k++)
            s_idx[buf * 2048 + tid + k * K1T] = pre[k];
        __syncthreads();

        int tn = t0 + TILE1;
        if (tn < s_end) {
            #pragma unroll
            for (int k = 0; k < 4; k++) {
                int j = tid + k * K1T;
                int samp = tn + (j >> 5);
                int v = NROWS - 1;
                if (samp < B) {
                    int r = j & 31;
                    v = is64 ? (int)x64[(size_t)samp * 32 + r]
                             : x32[samp * 32 + r];
                }
                pre[k] = v;
            }
        }

        const int* idx = &s_idx[buf * 2048 + s * 32];

        unsigned long long a0 = 0ull, a1 = 0ull, a2 = 0ull, a3 = 0ull;
        #pragma unroll
        for (int r0 = 0; r0 < 32; r0 += 8) {
            int id[8];
            #pragma unroll
            for (int k = 0; k < 8; k++) id[k] = idx[r0 + k];
            uint4 v[8];
            #pragma unroll
            for (int k = 0; k < 8; k++) v[k] = tab4[id[k] * 8 + q];

            // depth-2 fp16 tree per component, then f32x2 accumulate
            #define TREE(COMP, ACC) do {                                         \
                __half2 d1 = __hadd2(__hadd2(H2(v[0].COMP), H2(v[1].COMP)),      \
                                     __hadd2(H2(v[2].COMP), H2(v[3].COMP)));     \
                __half2 d2 = __hadd2(__hadd2(H2(v[4].COMP), H2(v[5].COMP)),      \
                                     __hadd2(H2(v[6].COMP), H2(v[7].COMP)));     \
                F2U t1_, t2_;                                                    \
                t1_.f = __half22float2(d1);                                      \
                t2_.f = __half22float2(d2);                                      \
                add2(ACC, t1_.u);                                                \
                add2(ACC, t2_.u);                                                \
            } while (0)

            TREE(x, a0);
            TREE(y, a1);
            TREE(z, a2);
            TREE(w, a3);
            #undef TREE
        }

        int samp = t0 + s;

        float h[8];
        {
            F2U u0, u1, u2, u3;
            u0.u = a0; u1.u = a1; u2.u = a2; u3.u = a3;
            h[0] = u0.f.x; h[1] = u0.f.y; h[2] = u1.f.x; h[3] = u1.f.y;
            h[4] = u2.f.x; h[5] = u2.f.y; h[6] = u3.f.x; h[7] = u3.f.y;
            const float4 b0 = ((const float4*)s_bias)[2 * q];
            const float4 b1 = ((const float4*)s_bias)[2 * q + 1];
            h[0] = screlu1(h[0] + b0.x); h[1] = screlu1(h[1] + b0.y);
            h[2] = screlu1(h[2] + b0.z); h[3] = screlu1(h[3] + b0.w);
            h[4] = screlu1(h[4] + b1.x); h[5] = screlu1(h[5] + b1.y);
            h[6] = screlu1(h[6] + b1.z); h[7] = screlu1(h[7] + b1.w);
        }

        // pair exchange: partner sample = s^1 -> lane^8 (same warp)
        float p[8];
        #pragma unroll
        for (int k = 0; k < 8; k++)
            p[k] = __shfl_xor_sync(0xffffffffu, h[k], 8);

        if (samp < B) {
            size_t pr = (size_t)(samp >> 1);
            float2* base = ghp + pr * HIDDEN + cbase + 8 * q + odd * 4;
            if (!odd) {
                ((float4*)base)[0] = make_float4(h[0], p[0], h[1], p[1]);
                ((float4*)base)[1] = make_float4(h[2], p[2], h[3], p[3]);
            } else {
                ((float4*)base)[0] = make_float4(p[4], h[4], p[5], h[5]);
                ((float4*)base)[1] = make_float4(p[6], h[6], p[7], h[7]);
            }
        }
        buf ^= 1;
        __syncthreads();   // idx buffer of this tile free before rewrite
    }
}

// ---------------------------------------------------------------------------
// K2: fc2 via sample-pair FFMA2; TRIPLE-buffered cp.async (wait_group 1),
// one barrier per chunk. 256 threads, 64 samples/block. (R12, frozen)
// ---------------------------------------------------------------------------
#define K2_OFF_H    0
#define K2_HBUF     16384              // 32 pairs * 64 ull * 8
#define K2_OFF_W    49152              // after 3 h buffers
#define K2_WBUF     8192               // 64 c * 32 j * 4
#define K2_OFF_CPW  73728              // after 3 w buffers
#define K2_OFF_WDLW 74752
#define K2_OFF_FB   77824
#define K2_OFF_CB   77952
#define K2_OFF_WB   77984
#define K2_OFF_NZ   78080
#define K2_SMEM     78096

__global__ __launch_bounds__(K2T)
void fc_kernel(const void* __restrict__ xv,
               const float* __restrict__ fc2_b,
               const float* __restrict__ cp_w,  const float* __restrict__ cp_b,
               const float* __restrict__ wdl_w, const float* __restrict__ wdl_b,
               const void* __restrict__ pcv, float* __restrict__ out, int B)
{
    extern __shared__ char smem[];
    const uint32_t sbase = smem_u32(smem);

    float* s_cp_w  = (float*)(smem + K2_OFF_CPW);
    float* s_wdl_w = (float*)(smem + K2_OFF_WDLW);
    float* s_fc2_b = (float*)(smem + K2_OFF_FB);
    float* s_cp_b  = (float*)(smem + K2_OFF_CB);
    float* s_wdl_b = (float*)(smem + K2_OFF_WB);
    int*   s_nz    = (int*)(smem + K2_OFF_NZ);

    const int tid = threadIdx.x;
    const int s0  = blockIdx.x * TS2;
    const int p0  = s0 >> 1;

    if (tid == 0) *s_nz = 0;
    __syncthreads();
    if (tid < 64) {
        if (((const unsigned int*)xv)[2 * tid + 1]) atomicOr(s_nz, 1);
    }
    for (int i = tid; i < 8 * 32; i += K2T)  s_cp_w[i]  = cp_w[i];
    for (int i = tid; i < 24 * 32; i += K2T) s_wdl_w[i] = wdl_w[i];
    if (tid < 32) s_fc2_b[tid] = fc2_b[tid];
    if (tid < 8)  s_cp_b[tid]  = cp_b[tid];
    if (tid < 24) s_wdl_b[tid] = wdl_b[tid];

    const float2* ghp = (const float2*)g_h;

    auto stage = [&](int k) {
        int buf = k % 3;
        int c0  = k * CHUNK2;
        uint32_t hdst = sbase + K2_OFF_H + buf * K2_HBUF;
        uint32_t wdst = sbase + K2_OFF_W + buf * K2_WBUF;
        #pragma unroll
        for (int r = 0; r < 4; r++) {
            int u   = tid + r * K2T;
            int p   = u >> 5;
            int c16 = u & 31;
            cp_async16(hdst + (uint32_t)(p * 512 + c16 * 16),
                       ghp + ((size_t)(p0 + p) * HIDDEN + c0 + c16 * 2));
        }
        const char* wsrc = (const char*)(g_wT + (size_t)c0 * 32);
        #pragma unroll
        for (int r = 0; r < 2; r++) {
            int u = tid + r * K2T;
            cp_async16(wdst + (uint32_t)(u * 16), wsrc + u * 16);
        }
        CP_COMMIT();
    };

    stage(0);
    stage(1);

    const int jq = tid & 15;
    const int sg = tid >> 4;

    unsigned long long acc00 = 0ull, acc01 = 0ull, acc10 = 0ull, acc11 = 0ull;

    for (int k = 0; k < NCH2; k++) {
        if (k == NCH2 - 1) { CP_WAIT0(); } else { CP_WAIT1(); }
        __syncthreads();
        if (k + 2 < NCH2) stage(k + 2);

        int buf = k % 3;
        const unsigned long long* hb =
            (const unsigned long long*)(smem + K2_OFF_H + buf * K2_HBUF);
        const float* wb = (const float*)(smem + K2_OFF_W + buf * K2_WBUF);
        const unsigned long long* h0 = hb + (2 * sg) * CHUNK2;
        const unsigned long long* h1 = hb + (2 * sg + 1) * CHUNK2;

        #pragma unroll 8
        for (int c = 0; c < CHUNK2; c++) {
            unsigned long long hv0 = h0[c];
            unsigned long long hv1 = h1[c];
            unsigned long long W0 = packdup(wb[c * 32 + 2 * jq]);
            unsigned long long W1 = packdup(wb[c * 32 + 2 * jq + 1]);
            fma2(acc00, hv0, W0);
            fma2(acc01, hv0, W1);
            fma2(acc10, hv1, W0);
            fma2(acc11, hv1, W1);
        }
    }

    __syncthreads();
    float* s_h2 = (float*)(smem + K2_OFF_H);
    {
        unsigned long long accs[2][2] = {{acc00, acc01}, {acc10, acc11}};
        #pragma unroll
        for (int p = 0; p < 2; p++) {
            #pragma unroll
            for (int jj = 0; jj < 2; jj++) {
                int j = 2 * jq + jj;
                F2U u; u.u = accs[p][jj];
                s_h2[(4 * sg + 2 * p)     * 33 + j] = screlu1(u.f.x + s_fc2_b[j]);
                s_h2[(4 * sg + 2 * p + 1) * 33 + j] = screlu1(u.f.y + s_fc2_b[j]);
            }
        }
    }
    __syncthreads();

    if (tid < TS2) {
        int samp = s0 + tid;
        if (samp < B) {
            const int is64 = (*s_nz == 0);
            int pc = is64 ? (int)((const long long*)pcv)[samp]
                          : ((const int*)pcv)[samp];
            int bkt = (pc - 2) * 8 / 30;
            bkt = max(0, min(7, bkt));

            const float* h2 = &s_h2[tid * 33];
            float cp = s_cp_b[bkt];
            float w0 = s_wdl_b[bkt * 3 + 0];
            float w1 = s_wdl_b[bkt * 3 + 1];
            float w2 = s_wdl_b[bkt * 3 + 2];
            const float* cw  = &s_cp_w[bkt * 32];
            const float* ww0 = &s_wdl_w[(bkt * 3 + 0) * 32];
            const float* ww1 = &s_wdl_w[(bkt * 3 + 1) * 32];
            const float* ww2 = &s_wdl_w[(bkt * 3 + 2) * 32];
            #pragma unroll
            for (int j = 0; j < 32; j++) {
                float hh = h2[j];
                cp = fmaf(hh, cw[j],  cp);
                w0 = fmaf(hh, ww0[j], w0);
                w1 = fmaf(hh, ww1[j], w1);
                w2 = fmaf(hh, ww2[j], w2);
            }
            out[samp] = cp;
            out[B + samp * 3 + 0] = w0;
            out[B + samp * 3 + 1] = w1;
            out[B + samp * 3 + 2] = w2;
        }
    }
}

// ---------------------------------------------------------------------------
extern "C" void kernel_launch(void* const* d_in, const int* in_sizes, int n_in,
                              void* d_out, int out_size)
{
    const void*  x      = d_in[0];
    const void*  pc     = d_in[1];
    const float* emb    = (const float*)d_in[2];
    const float* bias1  = (const float*)d_in[3];
    const float* fc2_w  = (const float*)d_in[4];
    const float* fc2_b  = (const float*)d_in[5];
    const float* cp_w   = (const float*)d_in[6];
    const float* cp_b   = (const float*)d_in[7];
    const float* wdl_w  = (const float*)d_in[8];
    const float* wdl_b  = (const float*)d_in[9];

    int B = in_sizes[0] / 32;
    if (B > MAX_B) B = MAX_B;

    prep_kernel<<<NROWS + 64, 512>>>(emb, fc2_w);

    cudaFuncSetAttribute(gather_kernel,
                         cudaFuncAttributeMaxDynamicSharedMemorySize, K1_SMEM);
    dim3 g1(NCHUNKS1, NGROUPS1);
    gather_kernel<<<g1, K1T, K1_SMEM>>>(x, bias1, B);

    cudaFuncSetAttribute(fc_kernel,
                         cudaFuncAttributeMaxDynamicSharedMemorySize, K2_SMEM);
    int g2 = (B + TS2 - 1) / TS2;
    fc_kernel<<<g2, K2T, K2_SMEM>>>(x, fc2_b, cp_w, cp_b, wdl_w, wdl_b,
                                    pc, (float*)d_out, B);
}

// round 14
// speedup vs baseline: 1.1094x; 1.1094x over previous
#include <cuda_runtime.h>
#include <cuda_fp16.h>
#include <cstdint>

// ---------------------------------------------------------------------------
// EvalNet: EmbeddingBag(sum,pad) -> screlu -> fc2(1024->32) -> screlu
//          -> bucketed cp/wdl heads.   (sm_100 SIMT)
// P : wT build only (64 blocks, ~2us).
// K1: R12 gather (CHUNK1=128), but table slice converted fp32->fp16 INLINE
//     during SMEM staging (no fp16 table in gmem, no emb prep pass).
// K2: R12 triple-buffered cp.async pipeline (frozen).
// ---------------------------------------------------------------------------

#define HIDDEN   1024
#define NROWS    769
#define MAX_B    16384
#define TILE     32

#define CHUNK1   128
#define NCHUNKS1 (HIDDEN / CHUNK1)   // 8
#define NGROUPS1 18                  // 8*18 = 144 blocks
#define K1T      512

#define K2T      256
#define TS2      64                  // samples per K2 block (grid 256)
#define CHUNK2   64
#define NCH2     (HIDDEN / CHUNK2)   // 16

__device__ float g_h[(size_t)MAX_B * HIDDEN];   // pair-interleaved hidden
__device__ float g_wT[HIDDEN * 32];             // wT[c*32+j] = fc2_w[j][c]

__device__ __forceinline__ float screlu1(float v)
{
    float c = fminf(fmaxf(v, 0.0f), 1.0f);
    return c * c;
}

__device__ __forceinline__ void fma2(unsigned long long& acc,
                                     unsigned long long a,
                                     unsigned long long b)
{
    asm("fma.rn.f32x2 %0, %1, %2, %0;" : "+l"(acc) : "l"(a), "l"(b));
}

__device__ __forceinline__ void add2(unsigned long long& acc,
                                     unsigned long long v)
{
    asm("add.rn.f32x2 %0, %0, %1;" : "+l"(acc) : "l"(v));
}

__device__ __forceinline__ unsigned long long packdup(float w)
{
    unsigned long long r;
    asm("mov.b64 %0, {%1, %1};" : "=l"(r) : "f"(w));
    return r;
}

__device__ __forceinline__ uint32_t smem_u32(const void* p)
{
    uint32_t a;
    asm("{ .reg .u64 t; cvta.to.shared.u64 t, %1; cvt.u32.u64 %0, t; }"
        : "=r"(a) : "l"(p));
    return a;
}

__device__ __forceinline__ void cp_async16(uint32_t dst, const void* src)
{
    asm volatile("cp.async.ca.shared.global [%0], [%1], 16;"
                 :: "r"(dst), "l"(__cvta_generic_to_global(src)));
}

#define CP_COMMIT() asm volatile("cp.async.commit_group;" ::: "memory")
#define CP_WAIT0()  asm volatile("cp.async.wait_group 0;" ::: "memory")
#define CP_WAIT1()  asm volatile("cp.async.wait_group 1;" ::: "memory")

union F2U { float2 f; unsigned long long u; };

#define H2(u) (*(const __half2*)&(u))

// ---------------------------------------------------------------------------
// P: wT build only. 64 blocks x 512 threads; coalesced reads and writes.
// ---------------------------------------------------------------------------
__global__ __launch_bounds__(512)
void prep_kernel(const float* __restrict__ fc2_w)
{
    int i = blockIdx.x * 512 + threadIdx.x;   // i = j*1024 + c
    int j = i >> 10, c = i & 1023;
    g_wT[c * 32 + j] = fc2_w[i];
}

// ---------------------------------------------------------------------------
// K1: gather + bias + screlu over a 128-col table slice; fp32->fp16
// conversion INLINE during staging. Gather core identical to R12.
// ---------------------------------------------------------------------------
__global__ __launch_bounds__(K1T)
void gather_kernel(const void* __restrict__ xv,
                   const float* __restrict__ emb,
                   const float* __restrict__ bias1,
                   int B)
{
    extern __shared__ char smem[];
    __half* s_tab  = (__half*)smem;                                  // NROWS*CHUNK1*2
    int*    s_idx  = (int*)(smem + NROWS * CHUNK1 * 2);              // 2*1024*4
    float*  s_bias = (float*)(smem + NROWS * CHUNK1 * 2 + 8192);     // CHUNK1*4
    int*    s_nz   = (int*)(smem + NROWS * CHUNK1 * 2 + 8192 + CHUNK1 * 4);

    const int tid   = threadIdx.x;
    const int cbase = blockIdx.x * CHUNK1;

    if (tid == 0) *s_nz = 0;
    __syncthreads();

    if (tid < 64) {
        if (((const unsigned int*)xv)[2 * tid + 1]) atomicOr(s_nz, 1);
    }

    // Stage + convert the table slice: 769 rows x 128 cols fp32 -> fp16.
    // Each i handles 8 fp32 (two float4) -> one uint4 of 8 halves.
    {
        uint4* dst = (uint4*)s_tab;               // row stride 16 uint4
        for (int i = tid; i < NROWS * 16; i += K1T) {
            int row = i >> 4, u = i & 15;
            const float4* src =
                (const float4*)(emb + (size_t)row * HIDDEN + cbase + u * 8);
            float4 a = src[0];
            float4 b = src[1];
            __half2 o[4];
            o[0] = __floats2half2_rn(a.x, a.y);
            o[1] = __floats2half2_rn(a.z, a.w);
            o[2] = __floats2half2_rn(b.x, b.y);
            o[3] = __floats2half2_rn(b.z, b.w);
            dst[i] = *(uint4*)o;
        }
    }
    if (tid < CHUNK1) s_bias[tid] = bias1[cbase + tid];
    __syncthreads();

    const int is64 = (*s_nz == 0);

    const int s   = tid >> 4;
    const int q   = tid & 15;
    const int odd = s & 1;

    const int spg     = (((B + NGROUPS1 - 1) / NGROUPS1) + TILE - 1) & ~(TILE - 1);
    const int s_begin = blockIdx.y * spg;
    const int s_end   = min(B, s_begin + spg);

    const int*       x32 = (const int*)xv;
    const long long* x64 = (const long long*)xv;
    float2*          ghp = (float2*)g_h;
    const uint4*     tab4 = (const uint4*)s_tab;

    int pre0 = NROWS - 1, pre1 = NROWS - 1;
    if (s_begin < s_end) {
        #pragma unroll
        for (int k = 0; k < 2; k++) {
            int j = tid + k * K1T;
            int samp = s_begin + (j >> 5);
            int v = NROWS - 1;
            if (samp < B) {
                int r = j & 31;
                v = is64 ? (int)x64[(size_t)samp * 32 + r]
                         : x32[samp * 32 + r];
            }
            if (k == 0) pre0 = v; else pre1 = v;
        }
    }

    int buf = 0;
    for (int t0 = s_begin; t0 < s_end; t0 += TILE) {
        s_idx[buf * 1024 + tid]       = pre0;
        s_idx[buf * 1024 + tid + K1T] = pre1;
        __syncthreads();

        int tn = t0 + TILE;
        if (tn < s_end) {
            #pragma unroll
            for (int k = 0; k < 2; k++) {
                int j = tid + k * K1T;
                int samp = tn + (j >> 5);
                int v = NROWS - 1;
                if (samp < B) {
                    int r = j & 31;
                    v = is64 ? (int)x64[(size_t)samp * 32 + r]
                             : x32[samp * 32 + r];
                }
                if (k == 0) pre0 = v; else pre1 = v;
            }
        }

        const int* idx = &s_idx[buf * 1024 + s * 32];

        unsigned long long a0 = 0ull, a1 = 0ull, a2 = 0ull, a3 = 0ull;
        #pragma unroll
        for (int r0 = 0; r0 < 32; r0 += 8) {
            int id[8];
            #pragma unroll
            for (int k = 0; k < 8; k++) id[k] = idx[r0 + k];
            uint4 v[8];
            #pragma unroll
            for (int k = 0; k < 8; k++) v[k] = tab4[id[k] * 16 + q];

            // depth-2 fp16 tree per component, then f32x2 accumulate
            #define TREE(COMP, ACC) do {                                         \
                __half2 d1 = __hadd2(__hadd2(H2(v[0].COMP), H2(v[1].COMP)),      \
                                     __hadd2(H2(v[2].COMP), H2(v[3].COMP)));     \
                __half2 d2 = __hadd2(__hadd2(H2(v[4].COMP), H2(v[5].COMP)),      \
                                     __hadd2(H2(v[6].COMP), H2(v[7].COMP)));     \
                F2U t1_, t2_;                                                    \
                t1_.f = __half22float2(d1);                                      \
                t2_.f = __half22float2(d2);                                      \
                add2(ACC, t1_.u);                                                \
                add2(ACC, t2_.u);                                                \
            } while (0)

            TREE(x, a0);
            TREE(y, a1);
            TREE(z, a2);
            TREE(w, a3);
            #undef TREE
        }

        int samp = t0 + s;

        float h[8];
        {
            F2U u0, u1, u2, u3;
            u0.u = a0; u1.u = a1; u2.u = a2; u3.u = a3;
            h[0] = u0.f.x; h[1] = u0.f.y; h[2] = u1.f.x; h[3] = u1.f.y;
            h[4] = u2.f.x; h[5] = u2.f.y; h[6] = u3.f.x; h[7] = u3.f.y;
            const float4 b0 = ((const float4*)s_bias)[2 * q];
            const float4 b1 = ((const float4*)s_bias)[2 * q + 1];
            h[0] = screlu1(h[0] + b0.x); h[1] = screlu1(h[1] + b0.y);
            h[2] = screlu1(h[2] + b0.z); h[3] = screlu1(h[3] + b0.w);
            h[4] = screlu1(h[4] + b1.x); h[5] = screlu1(h[5] + b1.y);
            h[6] = screlu1(h[6] + b1.z); h[7] = screlu1(h[7] + b1.w);
        }

        float p[8];
        #pragma unroll
        for (int k = 0; k < 8; k++)
            p[k] = __shfl_xor_sync(0xffffffffu, h[k], 16);

        if (samp < B) {
            size_t pr = (size_t)(samp >> 1);
            float2* base = ghp + pr * HIDDEN + cbase + 8 * q + odd * 4;
            if (!odd) {
                ((float4*)base)[0] = make_float4(h[0], p[0], h[1], p[1]);
                ((float4*)base)[1] = make_float4(h[2], p[2], h[3], p[3]);
            } else {
                ((float4*)base)[0] = make_float4(p[4], h[4], p[5], h[5]);
                ((float4*)base)[1] = make_float4(p[6], h[6], p[7], h[7]);
            }
        }
        buf ^= 1;
    }
}

// ---------------------------------------------------------------------------
// K2: fc2 via sample-pair FFMA2; TRIPLE-buffered cp.async (wait_group 1),
// one barrier per chunk. 256 threads, 64 samples/block. (R12, frozen)
// ---------------------------------------------------------------------------
#define K2_OFF_H    0
#define K2_HBUF     16384              // 32 pairs * 64 ull * 8
#define K2_OFF_W    49152              // after 3 h buffers
#define K2_WBUF     8192               // 64 c * 32 j * 4
#define K2_OFF_CPW  73728              // after 3 w buffers
#define K2_OFF_WDLW 74752
#define K2_OFF_FB   77824
#define K2_OFF_CB   77952
#define K2_OFF_WB   77984
#define K2_OFF_NZ   78080
#define K2_SMEM     78096

__global__ __launch_bounds__(K2T)
void fc_kernel(const void* __restrict__ xv,
               const float* __restrict__ fc2_b,
               const float* __restrict__ cp_w,  const float* __restrict__ cp_b,
               const float* __restrict__ wdl_w, const float* __restrict__ wdl_b,
               const void* __restrict__ pcv, float* __restrict__ out, int B)
{
    extern __shared__ char smem[];
    const uint32_t sbase = smem_u32(smem);

    float* s_cp_w  = (float*)(smem + K2_OFF_CPW);
    float* s_wdl_w = (float*)(smem + K2_OFF_WDLW);
    float* s_fc2_b = (float*)(smem + K2_OFF_FB);
    float* s_cp_b  = (float*)(smem + K2_OFF_CB);
    float* s_wdl_b = (float*)(smem + K2_OFF_WB);
    int*   s_nz    = (int*)(smem + K2_OFF_NZ);

    const int tid = threadIdx.x;
    const int s0  = blockIdx.x * TS2;
    const int p0  = s0 >> 1;

    if (tid == 0) *s_nz = 0;
    __syncthreads();
    if (tid < 64) {
        if (((const unsigned int*)xv)[2 * tid + 1]) atomicOr(s_nz, 1);
    }
    for (int i = tid; i < 8 * 32; i += K2T)  s_cp_w[i]  = cp_w[i];
    for (int i = tid; i < 24 * 32; i += K2T) s_wdl_w[i] = wdl_w[i];
    if (tid < 32) s_fc2_b[tid] = fc2_b[tid];
    if (tid < 8)  s_cp_b[tid]  = cp_b[tid];
    if (tid < 24) s_wdl_b[tid] = wdl_b[tid];

    const float2* ghp = (const float2*)g_h;

    auto stage = [&](int k) {
        int buf = k % 3;
        int c0  = k * CHUNK2;
        uint32_t hdst = sbase + K2_OFF_H + buf * K2_HBUF;
        uint32_t wdst = sbase + K2_OFF_W + buf * K2_WBUF;
        #pragma unroll
        for (int r = 0; r < 4; r++) {
            int u   = tid + r * K2T;
            int p   = u >> 5;
            int c16 = u & 31;
            cp_async16(hdst + (uint32_t)(p * 512 + c16 * 16),
                       ghp + ((size_t)(p0 + p) * HIDDEN + c0 + c16 * 2));
        }
        const char* wsrc = (const char*)(g_wT + (size_t)c0 * 32);
        #pragma unroll
        for (int r = 0; r < 2; r++) {
            int u = tid + r * K2T;
            cp_async16(wdst + (uint32_t)(u * 16), wsrc + u * 16);
        }
        CP_COMMIT();
    };

    stage(0);
    stage(1);

    const int jq = tid & 15;
    const int sg = tid >> 4;

    unsigned long long acc00 = 0ull, acc01 = 0ull, acc10 = 0ull, acc11 = 0ull;

    for (int k = 0; k < NCH2; k++) {
        if (k == NCH2 - 1) { CP_WAIT0(); } else { CP_WAIT1(); }
        __syncthreads();
        if (k + 2 < NCH2) stage(k + 2);

        int buf = k % 3;
        const unsigned long long* hb =
            (const unsigned long long*)(smem + K2_OFF_H + buf * K2_HBUF);
        const float* wb = (const float*)(smem + K2_OFF_W + buf * K2_WBUF);
        const unsigned long long* h0 = hb + (2 * sg) * CHUNK2;
        const unsigned long long* h1 = hb + (2 * sg + 1) * CHUNK2;

        #pragma unroll 8
        for (int c = 0; c < CHUNK2; c++) {
            unsigned long long hv0 = h0[c];
            unsigned long long hv1 = h1[c];
            unsigned long long W0 = packdup(wb[c * 32 + 2 * jq]);
            unsigned long long W1 = packdup(wb[c * 32 + 2 * jq + 1]);
            fma2(acc00, hv0, W0);
            fma2(acc01, hv0, W1);
            fma2(acc10, hv1, W0);
            fma2(acc11, hv1, W1);
        }
    }

    __syncthreads();
    float* s_h2 = (float*)(smem + K2_OFF_H);
    {
        unsigned long long accs[2][2] = {{acc00, acc01}, {acc10, acc11}};
        #pragma unroll
        for (int p = 0; p < 2; p++) {
            #pragma unroll
            for (int jj = 0; jj < 2; jj++) {
                int j = 2 * jq + jj;
                F2U u; u.u = accs[p][jj];
                s_h2[(4 * sg + 2 * p)     * 33 + j] = screlu1(u.f.x + s_fc2_b[j]);
                s_h2[(4 * sg + 2 * p + 1) * 33 + j] = screlu1(u.f.y + s_fc2_b[j]);
            }
        }
    }
    __syncthreads();

    if (tid < TS2) {
        int samp = s0 + tid;
        if (samp < B) {
            const int is64 = (*s_nz == 0);
            int pc = is64 ? (int)((const long long*)pcv)[samp]
                          : ((const int*)pcv)[samp];
            int bkt = (pc - 2) * 8 / 30;
            bkt = max(0, min(7, bkt));

            const float* h2 = &s_h2[tid * 33];
            float cp = s_cp_b[bkt];
            float w0 = s_wdl_b[bkt * 3 + 0];
            float w1 = s_wdl_b[bkt * 3 + 1];
            float w2 = s_wdl_b[bkt * 3 + 2];
            const float* cw  = &s_cp_w[bkt * 32];
            const float* ww0 = &s_wdl_w[(bkt * 3 + 0) * 32];
            const float* ww1 = &s_wdl_w[(bkt * 3 + 1) * 32];
            const float* ww2 = &s_wdl_w[(bkt * 3 + 2) * 32];
            #pragma unroll
            for (int j = 0; j < 32; j++) {
                float hh = h2[j];
                cp = fmaf(hh, cw[j],  cp);
                w0 = fmaf(hh, ww0[j], w0);
                w1 = fmaf(hh, ww1[j], w1);
                w2 = fmaf(hh, ww2[j], w2);
            }
            out[samp] = cp;
            out[B + samp * 3 + 0] = w0;
            out[B + samp * 3 + 1] = w1;
            out[B + samp * 3 + 2] = w2;
        }
    }
}

// ---------------------------------------------------------------------------
extern "C" void kernel_launch(void* const* d_in, const int* in_sizes, int n_in,
                              void* d_out, int out_size)
{
    const void*  x      = d_in[0];
    const void*  pc     = d_in[1];
    const float* emb    = (const float*)d_in[2];
    const float* bias1  = (const float*)d_in[3];
    const float* fc2_w  = (const float*)d_in[4];
    const float* fc2_b  = (const float*)d_in[5];
    const float* cp_w   = (const float*)d_in[6];
    const float* cp_b   = (const float*)d_in[7];
    const float* wdl_w  = (const float*)d_in[8];
    const float* wdl_b  = (const float*)d_in[9];

    int B = in_sizes[0] / 32;
    if (B > MAX_B) B = MAX_B;

    prep_kernel<<<64, 512>>>(fc2_w);

    const int k1_smem = NROWS * CHUNK1 * 2 + 8192 + CHUNK1 * 4 + 16;
    cudaFuncSetAttribute(gather_kernel,
                         cudaFuncAttributeMaxDynamicSharedMemorySize, k1_smem);
    dim3 g1(NCHUNKS1, NGROUPS1);
    gather_kernel<<<g1, K1T, k1_smem>>>(x, emb, bias1, B);

    cudaFuncSetAttribute(fc_kernel,
                         cudaFuncAttributeMaxDynamicSharedMemorySize, K2_SMEM);
    int g2 = (B + TS2 - 1) / TS2;
    fc_kernel<<<g2, K2T, K2_SMEM>>>(x, fc2_b, cp_w, cp_b, wdl_w, wdl_b,
                                    pc, (float*)d_out, B);
}

// round 15
// speedup vs baseline: 1.1438x; 1.0310x over previous
#include <cuda_runtime.h>
#include <cuda_fp16.h>
#include <cstdint>

// ---------------------------------------------------------------------------
// EvalNet: EmbeddingBag(sum,pad) -> screlu -> fc2(1024->32) -> screlu
//          -> bucketed cp/wdl heads.   (sm_100 SIMT)
// P : emb fp32->fp16 (769 blocks); wT build (64 blocks).   [R12]
// K1: R12 gather (CHUNK1=128) but TWO 32-sample sub-tiles per barrier
//     (2048 idx staged per sync; barrier count halved).
// K2: R12 triple-buffered cp.async pipeline (frozen).
// ---------------------------------------------------------------------------

#define HIDDEN   1024
#define NROWS    769
#define MAX_B    16384
#define TILE     32

#define CHUNK1   128
#define NCHUNKS1 (HIDDEN / CHUNK1)   // 8
#define NGROUPS1 18                  // 8*18 = 144 blocks
#define K1T      512

#define K2T      256
#define TS2      64                  // samples per K2 block (grid 256)
#define CHUNK2   64
#define NCH2     (HIDDEN / CHUNK2)   // 16

__device__ float  g_h[(size_t)MAX_B * HIDDEN];   // pair-interleaved hidden
__device__ __half g_emb_h[NROWS * HIDDEN];       // fp16 table
__device__ float  g_wT[HIDDEN * 32];             // wT[c*32+j] = fc2_w[j][c]

__device__ __forceinline__ float screlu1(float v)
{
    float c = fminf(fmaxf(v, 0.0f), 1.0f);
    return c * c;
}

__device__ __forceinline__ void fma2(unsigned long long& acc,
                                     unsigned long long a,
                                     unsigned long long b)
{
    asm("fma.rn.f32x2 %0, %1, %2, %0;" : "+l"(acc) : "l"(a), "l"(b));
}

__device__ __forceinline__ void add2(unsigned long long& acc,
                                     unsigned long long v)
{
    asm("add.rn.f32x2 %0, %0, %1;" : "+l"(acc) : "l"(v));
}

__device__ __forceinline__ unsigned long long packdup(float w)
{
    unsigned long long r;
    asm("mov.b64 %0, {%1, %1};" : "=l"(r) : "f"(w));
    return r;
}

__device__ __forceinline__ uint32_t smem_u32(const void* p)
{
    uint32_t a;
    asm("{ .reg .u64 t; cvta.to.shared.u64 t, %1; cvt.u32.u64 %0, t; }"
        : "=r"(a) : "l"(p));
    return a;
}

__device__ __forceinline__ void cp_async16(uint32_t dst, const void* src)
{
    asm volatile("cp.async.ca.shared.global [%0], [%1], 16;"
                 :: "r"(dst), "l"(__cvta_generic_to_global(src)));
}

#define CP_COMMIT() asm volatile("cp.async.commit_group;" ::: "memory")
#define CP_WAIT0()  asm volatile("cp.async.wait_group 0;" ::: "memory")
#define CP_WAIT1()  asm volatile("cp.async.wait_group 1;" ::: "memory")

union F2U { float2 f; unsigned long long u; };

#define H2(u) (*(const __half2*)&(u))

// ---------------------------------------------------------------------------
// P: blocks 0..768: emb row -> fp16; blocks 769..832: wT build.
// ---------------------------------------------------------------------------
__global__ __launch_bounds__(512)
void prep_kernel(const float* __restrict__ emb,
                 const float* __restrict__ fc2_w)
{
    const int b = blockIdx.x, tid = threadIdx.x;
    if (b < NROWS) {
        const float2* src = (const float2*)(emb + b * HIDDEN);
        __half2* dst = (__half2*)(g_emb_h + b * HIDDEN);
        dst[tid] = __floats2half2_rn(src[tid].x, src[tid].y);
    } else {
        int i = (b - NROWS) * 512 + tid;
        int j = i >> 10, c = i & 1023;
        g_wT[c * 32 + j] = fc2_w[i];
    }
}

// ---------------------------------------------------------------------------
// K1: gather + bias + screlu over a 128-col fp16 table slice.
// TWO 32-sample sub-tiles per barrier; per-sub-tile gather identical to R12.
// smem: tab 197KB + idx 2*2048 ints (16KB) + bias + nz  ≈ 213.6 KB.
// ---------------------------------------------------------------------------
#define K1_IDX_OFF  (NROWS * CHUNK1 * 2)
#define K1_BIAS_OFF (K1_IDX_OFF + 2 * 2048 * 4)
#define K1_NZ_OFF   (K1_BIAS_OFF + CHUNK1 * 4)
#define K1_SMEM     (K1_NZ_OFF + 16)

__global__ __launch_bounds__(K1T)
void gather_kernel(const void* __restrict__ xv,
                   const float* __restrict__ bias1,
                   int B)
{
    extern __shared__ char smem[];
    __half* s_tab  = (__half*)smem;
    int*    s_idx  = (int*)(smem + K1_IDX_OFF);
    float*  s_bias = (float*)(smem + K1_BIAS_OFF);
    int*    s_nz   = (int*)(smem + K1_NZ_OFF);

    const int tid   = threadIdx.x;
    const int cbase = blockIdx.x * CHUNK1;

    if (tid == 0) *s_nz = 0;
    __syncthreads();

    if (tid < 64) {
        if (((const unsigned int*)xv)[2 * tid + 1]) atomicOr(s_nz, 1);
    }

    // Stage the fp16 table slice: 769 rows x 128 cols = 16 uint4 per row.
    {
        const uint4* src = (const uint4*)g_emb_h;     // row stride 128 uint4
        uint4*       dst = (uint4*)s_tab;             // row stride 16 uint4
        const int cb8 = cbase >> 3;
        for (int i = tid; i < NROWS * 16; i += K1T) {
            int row = i >> 4, u = i & 15;
            dst[i] = src[row * 128 + cb8 + u];
        }
    }
    if (tid < CHUNK1) s_bias[tid] = bias1[cbase + tid];
    __syncthreads();

    const int is64 = (*s_nz == 0);

    const int s   = tid >> 4;     // sample within sub-tile (0..31)
    const int q   = tid & 15;     // 16B column group
    const int odd = s & 1;

    const int spg     = (((B + NGROUPS1 - 1) / NGROUPS1) + TILE - 1) & ~(TILE - 1);
    const int s_begin = blockIdx.y * spg;
    const int s_end   = min(B, s_begin + spg);

    const int*       x32 = (const int*)xv;
    const long long* x64 = (const long long*)xv;
    float2*          ghp = (float2*)g_h;
    const uint4*     tab4 = (const uint4*)s_tab;

    // preload first tile-pair's indices (4 regs = 2048 ints)
    int pre[4] = {NROWS - 1, NROWS - 1, NROWS - 1, NROWS - 1};
    if (s_begin < s_end) {
        #pragma unroll
        for (int k = 0; k < 4; k++) {
            int j = tid + k * K1T;
            int samp = s_begin + (j >> 5);
            int v = NROWS - 1;
            if (samp < B) {
                int r = j & 31;
                v = is64 ? (int)x64[(size_t)samp * 32 + r]
                         : x32[samp * 32 + r];
            }
            pre[k] = v;
        }
    }

    int buf = 0;
    for (int t0 = s_begin; t0 < s_end; t0 += 2 * TILE) {
        #pragma unroll
        for (int k = 0; k < 4; k++)
            s_idx[buf * 2048 + tid + k * K1T] = pre[k];
        __syncthreads();

        // prefetch next tile-pair's indices (overlaps gather below)
        int tn = t0 + 2 * TILE;
        if (tn < s_end) {
            #pragma unroll
            for (int k = 0; k < 4; k++) {
                int j = tid + k * K1T;
                int samp = tn + (j >> 5);
                int v = NROWS - 1;
                if (samp < B) {
                    int r = j & 31;
                    v = is64 ? (int)x64[(size_t)samp * 32 + r]
                             : x32[samp * 32 + r];
                }
                pre[k] = v;
            }
        }

        // two sub-tiles, registers reused serially
        #pragma unroll
        for (int sub = 0; sub < 2; sub++) {
            int sbase_t = t0 + sub * TILE;
            const int* idx = &s_idx[buf * 2048 + sub * 1024 + s * 32];

            unsigned long long a0 = 0ull, a1 = 0ull, a2 = 0ull, a3 = 0ull;
            #pragma unroll
            for (int r0 = 0; r0 < 32; r0 += 8) {
                int id[8];
                #pragma unroll
                for (int k = 0; k < 8; k++) id[k] = idx[r0 + k];
                uint4 v[8];
                #pragma unroll
                for (int k = 0; k < 8; k++) v[k] = tab4[id[k] * 16 + q];

                #define TREE(COMP, ACC) do {                                     \
                    __half2 d1 = __hadd2(__hadd2(H2(v[0].COMP), H2(v[1].COMP)),  \
                                         __hadd2(H2(v[2].COMP), H2(v[3].COMP))); \
                    __half2 d2 = __hadd2(__hadd2(H2(v[4].COMP), H2(v[5].COMP)),  \
                                         __hadd2(H2(v[6].COMP), H2(v[7].COMP))); \
                    F2U t1_, t2_;                                                \
                    t1_.f = __half22float2(d1);                                  \
                    t2_.f = __half22float2(d2);                                  \
                    add2(ACC, t1_.u);                                            \
                    add2(ACC, t2_.u);                                            \
                } while (0)

                TREE(x, a0);
                TREE(y, a1);
                TREE(z, a2);
                TREE(w, a3);
                #undef TREE
            }

            int samp = sbase_t + s;

            float h[8];
            {
                F2U u0, u1, u2, u3;
                u0.u = a0; u1.u = a1; u2.u = a2; u3.u = a3;
                h[0] = u0.f.x; h[1] = u0.f.y; h[2] = u1.f.x; h[3] = u1.f.y;
                h[4] = u2.f.x; h[5] = u2.f.y; h[6] = u3.f.x; h[7] = u3.f.y;
                const float4 b0 = ((const float4*)s_bias)[2 * q];
                const float4 b1 = ((const float4*)s_bias)[2 * q + 1];
                h[0] = screlu1(h[0] + b0.x); h[1] = screlu1(h[1] + b0.y);
                h[2] = screlu1(h[2] + b0.z); h[3] = screlu1(h[3] + b0.w);
                h[4] = screlu1(h[4] + b1.x); h[5] = screlu1(h[5] + b1.y);
                h[6] = screlu1(h[6] + b1.z); h[7] = screlu1(h[7] + b1.w);
            }

            float p[8];
            #pragma unroll
            for (int k = 0; k < 8; k++)
                p[k] = __shfl_xor_sync(0xffffffffu, h[k], 16);

            if (samp < s_end) {
                size_t pr = (size_t)(samp >> 1);
                float2* base = ghp + pr * HIDDEN + cbase + 8 * q + odd * 4;
                if (!odd) {
                    ((float4*)base)[0] = make_float4(h[0], p[0], h[1], p[1]);
                    ((float4*)base)[1] = make_float4(h[2], p[2], h[3], p[3]);
                } else {
                    ((float4*)base)[0] = make_float4(p[4], h[4], p[5], h[5]);
                    ((float4*)base)[1] = make_float4(p[6], h[6], p[7], h[7]);
                }
            }
        }
        buf ^= 1;
    }
}

// ---------------------------------------------------------------------------
// K2: fc2 via sample-pair FFMA2; TRIPLE-buffered cp.async (wait_group 1),
// one barrier per chunk. 256 threads, 64 samples/block. (R12, frozen)
// ---------------------------------------------------------------------------
#define K2_OFF_H    0
#define K2_HBUF     16384              // 32 pairs * 64 ull * 8
#define K2_OFF_W    49152              // after 3 h buffers
#define K2_WBUF     8192               // 64 c * 32 j * 4
#define K2_OFF_CPW  73728              // after 3 w buffers
#define K2_OFF_WDLW 74752
#define K2_OFF_FB   77824
#define K2_OFF_CB   77952
#define K2_OFF_WB   77984
#define K2_OFF_NZ   78080
#define K2_SMEM     78096

__global__ __launch_bounds__(K2T)
void fc_kernel(const void* __restrict__ xv,
               const float* __restrict__ fc2_b,
               const float* __restrict__ cp_w,  const float* __restrict__ cp_b,
               const float* __restrict__ wdl_w, const float* __restrict__ wdl_b,
               const void* __restrict__ pcv, float* __restrict__ out, int B)
{
    extern __shared__ char smem[];
    const uint32_t sbase = smem_u32(smem);

    float* s_cp_w  = (float*)(smem + K2_OFF_CPW);
    float* s_wdl_w = (float*)(smem + K2_OFF_WDLW);
    float* s_fc2_b = (float*)(smem + K2_OFF_FB);
    float* s_cp_b  = (float*)(smem + K2_OFF_CB);
    float* s_wdl_b = (float*)(smem + K2_OFF_WB);
    int*   s_nz    = (int*)(smem + K2_OFF_NZ);

    const int tid = threadIdx.x;
    const int s0  = blockIdx.x * TS2;
    const int p0  = s0 >> 1;

    if (tid == 0) *s_nz = 0;
    __syncthreads();
    if (tid < 64) {
        if (((const unsigned int*)xv)[2 * tid + 1]) atomicOr(s_nz, 1);
    }
    for (int i = tid; i < 8 * 32; i += K2T)  s_cp_w[i]  = cp_w[i];
    for (int i = tid; i < 24 * 32; i += K2T) s_wdl_w[i] = wdl_w[i];
    if (tid < 32) s_fc2_b[tid] = fc2_b[tid];
    if (tid < 8)  s_cp_b[tid]  = cp_b[tid];
    if (tid < 24) s_wdl_b[tid] = wdl_b[tid];

    const float2* ghp = (const float2*)g_h;

    auto stage = [&](int k) {
        int buf = k % 3;
        int c0  = k * CHUNK2;
        uint32_t hdst = sbase + K2_OFF_H + buf * K2_HBUF;
        uint32_t wdst = sbase + K2_OFF_W + buf * K2_WBUF;
        #pragma unroll
        for (int r = 0; r < 4; r++) {
            int u   = tid + r * K2T;
            int p   = u >> 5;
            int c16 = u & 31;
            cp_async16(hdst + (uint32_t)(p * 512 + c16 * 16),
                       ghp + ((size_t)(p0 + p) * HIDDEN + c0 + c16 * 2));
        }
        const char* wsrc = (const char*)(g_wT + (size_t)c0 * 32);
        #pragma unroll
        for (int r = 0; r < 2; r++) {
            int u = tid + r * K2T;
            cp_async16(wdst + (uint32_t)(u * 16), wsrc + u * 16);
        }
        CP_COMMIT();
    };

    stage(0);
    stage(1);

    const int jq = tid & 15;
    const int sg = tid >> 4;

    unsigned long long acc00 = 0ull, acc01 = 0ull, acc10 = 0ull, acc11 = 0ull;

    for (int k = 0; k < NCH2; k++) {
        if (k == NCH2 - 1) { CP_WAIT0(); } else { CP_WAIT1(); }
        __syncthreads();
        if (k + 2 < NCH2) stage(k + 2);

        int buf = k % 3;
        const unsigned long long* hb =
            (const unsigned long long*)(smem + K2_OFF_H + buf * K2_HBUF);
        const float* wb = (const float*)(smem + K2_OFF_W + buf * K2_WBUF);
        const unsigned long long* h0 = hb + (2 * sg) * CHUNK2;
        const unsigned long long* h1 = hb + (2 * sg + 1) * CHUNK2;

        #pragma unroll 8
        for (int c = 0; c < CHUNK2; c++) {
            unsigned long long hv0 = h0[c];
            unsigned long long hv1 = h1[c];
            unsigned long long W0 = packdup(wb[c * 32 + 2 * jq]);
            unsigned long long W1 = packdup(wb[c * 32 + 2 * jq + 1]);
            fma2(acc00, hv0, W0);
            fma2(acc01, hv0, W1);
            fma2(acc10, hv1, W0);
            fma2(acc11, hv1, W1);
        }
    }

    __syncthreads();
    float* s_h2 = (float*)(smem + K2_OFF_H);
    {
        unsigned long long accs[2][2] = {{acc00, acc01}, {acc10, acc11}};
        #pragma unroll
        for (int p = 0; p < 2; p++) {
            #pragma unroll
            for (int jj = 0; jj < 2; jj++) {
                int j = 2 * jq + jj;
                F2U u; u.u = accs[p][jj];
                s_h2[(4 * sg + 2 * p)     * 33 + j] = screlu1(u.f.x + s_fc2_b[j]);
                s_h2[(4 * sg + 2 * p + 1) * 33 + j] = screlu1(u.f.y + s_fc2_b[j]);
            }
        }
    }
    __syncthreads();

    if (tid < TS2) {
        int samp = s0 + tid;
        if (samp < B) {
            const int is64 = (*s_nz == 0);
            int pc = is64 ? (int)((const long long*)pcv)[samp]
                          : ((const int*)pcv)[samp];
            int bkt = (pc - 2) * 8 / 30;
            bkt = max(0, min(7, bkt));

            const float* h2 = &s_h2[tid * 33];
            float cp = s_cp_b[bkt];
            float w0 = s_wdl_b[bkt * 3 + 0];
            float w1 = s_wdl_b[bkt * 3 + 1];
            float w2 = s_wdl_b[bkt * 3 + 2];
            const float* cw  = &s_cp_w[bkt * 32];
            const float* ww0 = &s_wdl_w[(bkt * 3 + 0) * 32];
            const float* ww1 = &s_wdl_w[(bkt * 3 + 1) * 32];
            const float* ww2 = &s_wdl_w[(bkt * 3 + 2) * 32];
            #pragma unroll
            for (int j = 0; j < 32; j++) {
                float hh = h2[j];
                cp = fmaf(hh, cw[j],  cp);
                w0 = fmaf(hh, ww0[j], w0);
                w1 = fmaf(hh, ww1[j], w1);
                w2 = fmaf(hh, ww2[j], w2);
            }
            out[samp] = cp;
            out[B + samp * 3 + 0] = w0;
            out[B + samp * 3 + 1] = w1;
            out[B + samp * 3 + 2] = w2;
        }
    }
}

// ---------------------------------------------------------------------------
extern "C" void kernel_launch(void* const* d_in, const int* in_sizes, int n_in,
                              void* d_out, int out_size)
{
    const void*  x      = d_in[0];
    const void*  pc     = d_in[1];
    const float* emb    = (const float*)d_in[2];
    const float* bias1  = (const float*)d_in[3];
    const float* fc2_w  = (const float*)d_in[4];
    const float* fc2_b  = (const float*)d_in[5];
    const float* cp_w   = (const float*)d_in[6];
    const float* cp_b   = (const float*)d_in[7];
    const float* wdl_w  = (const float*)d_in[8];
    const float* wdl_b  = (const float*)d_in[9];

    int B = in_sizes[0] / 32;
    if (B > MAX_B) B = MAX_B;

    prep_kernel<<<NROWS + 64, 512>>>(emb, fc2_w);

    cudaFuncSetAttribute(gather_kernel,
                         cudaFuncAttributeMaxDynamicSharedMemorySize, K1_SMEM);
    dim3 g1(NCHUNKS1, NGROUPS1);
    gather_kernel<<<g1, K1T, K1_SMEM>>>(x, bias1, B);

    cudaFuncSetAttribute(fc_kernel,
                         cudaFuncAttributeMaxDynamicSharedMemorySize, K2_SMEM);
    int g2 = (B + TS2 - 1) / TS2;
    fc_kernel<<<g2, K2T, K2_SMEM>>>(x, fc2_b, cp_w, cp_b, wdl_w, wdl_b,
                                    pc, (float*)d_out, B);
}

// round 16
// speedup vs baseline: 1.7905x; 1.5653x over previous
#include <cuda_runtime.h>
#include <cuda_fp16.h>
#include <cstdint>

// ---------------------------------------------------------------------------
// EvalNet: EmbeddingBag(sum,pad) -> screlu -> fc2(1024->32) -> screlu
//          -> bucketed cp/wdl heads.   (sm_100 SIMT + warp-level HMMA)
// P : emb fp32->fp16 (769 blocks); fc2_w fp32->fp16 (32 blocks).
// K1: R6 gather (fp16 table, depth-1 HADD2, f32x2 acc); h stored fp16
//     ROW-MAJOR g_hh[samp][c].
// K2: warp-level mma.sync m16n8k16 GEMM h[128,1024] @ w^T -> [128,32] fp32,
//     triple-buffered cp.async h chunks, w staged once; screlu + heads.
// ---------------------------------------------------------------------------

#define HIDDEN   1024
#define NROWS    769
#define MAX_B    16384
#define TILE     32

#define CHUNK1   128
#define NCHUNKS1 (HIDDEN / CHUNK1)   // 8
#define NGROUPS1 18                  // 144 blocks
#define K1T      512

#define K2T      256                 // 8 warps
#define MT       128                 // samples per K2 block
#define CK       64                  // K per staged chunk
#define NCH      (HIDDEN / CK)       // 16

__device__ __half g_emb_h[NROWS * HIDDEN];       // fp16 table
__device__ __half g_hh[(size_t)MAX_B * HIDDEN];  // fp16 hidden, row-major
__device__ __half g_w_h[32 * HIDDEN];            // fp16 fc2_w (row-major j,c)

__device__ __forceinline__ float screlu1(float v)
{
    float c = fminf(fmaxf(v, 0.0f), 1.0f);
    return c * c;
}

__device__ __forceinline__ void add2(unsigned long long& acc,
                                     unsigned long long v)
{
    asm("add.rn.f32x2 %0, %0, %1;" : "+l"(acc) : "l"(v));
}

__device__ __forceinline__ uint32_t smem_u32(const void* p)
{
    uint32_t a;
    asm("{ .reg .u64 t; cvta.to.shared.u64 t, %1; cvt.u32.u64 %0, t; }"
        : "=r"(a) : "l"(p));
    return a;
}

__device__ __forceinline__ void cp_async16(uint32_t dst, const void* src)
{
    asm volatile("cp.async.ca.shared.global [%0], [%1], 16;"
                 :: "r"(dst), "l"(__cvta_generic_to_global(src)));
}

#define CP_COMMIT() asm volatile("cp.async.commit_group;" ::: "memory")
#define CP_WAIT0()  asm volatile("cp.async.wait_group 0;" ::: "memory")
#define CP_WAIT1()  asm volatile("cp.async.wait_group 1;" ::: "memory")

union F2U { float2 f; unsigned long long u; };

// ---------------------------------------------------------------------------
// P: blocks 0..768: emb row -> fp16; blocks 769..800: fc2_w -> fp16.
// ---------------------------------------------------------------------------
__global__ __launch_bounds__(512)
void prep_kernel(const float* __restrict__ emb,
                 const float* __restrict__ fc2_w)
{
    const int b = blockIdx.x, tid = threadIdx.x;
    if (b < NROWS) {
        const float2* src = (const float2*)(emb + b * HIDDEN);
        __half2* dst = (__half2*)(g_emb_h + b * HIDDEN);
        dst[tid] = __floats2half2_rn(src[tid].x, src[tid].y);
    } else {
        int i = (b - NROWS) * 512 + tid;      // 32 blocks * 512 = 16384 half2
        float2 v = ((const float2*)fc2_w)[i];
        ((__half2*)g_w_h)[i] = __floats2half2_rn(v.x, v.y);
    }
}

// ---------------------------------------------------------------------------
// K1: gather + bias + screlu over a 128-col fp16 table slice (R6 core);
// h written fp16 row-major.
// ---------------------------------------------------------------------------
__global__ __launch_bounds__(K1T)
void gather_kernel(const void* __restrict__ xv,
                   const float* __restrict__ bias1,
                   int B)
{
    extern __shared__ char smem[];
    __half* s_tab  = (__half*)smem;                                  // NROWS*CHUNK1*2
    int*    s_idx  = (int*)(smem + NROWS * CHUNK1 * 2);              // 2*1024*4
    float*  s_bias = (float*)(smem + NROWS * CHUNK1 * 2 + 8192);     // CHUNK1*4
    int*    s_nz   = (int*)(smem + NROWS * CHUNK1 * 2 + 8192 + CHUNK1 * 4);

    const int tid   = threadIdx.x;
    const int cbase = blockIdx.x * CHUNK1;

    if (tid == 0) *s_nz = 0;
    __syncthreads();

    if (tid < 64) {
        if (((const unsigned int*)xv)[2 * tid + 1]) atomicOr(s_nz, 1);
    }

    {
        const uint4* src = (const uint4*)g_emb_h;       // row stride 128 uint4
        uint4*       dst = (uint4*)s_tab;               // row stride 16 uint4
        const int cb8 = cbase >> 3;
        for (int i = tid; i < NROWS * 16; i += K1T) {
            int row = i >> 4, u = i & 15;
            dst[i] = src[row * 128 + cb8 + u];
        }
    }
    if (tid < CHUNK1) s_bias[tid] = bias1[cbase + tid];
    __syncthreads();

    const int is64 = (*s_nz == 0);

    const int s = tid >> 4;
    const int q = tid & 15;

    const int spg     = (((B + NGROUPS1 - 1) / NGROUPS1) + TILE - 1) & ~(TILE - 1);
    const int s_begin = blockIdx.y * spg;
    const int s_end   = min(B, s_begin + spg);

    const int*       x32 = (const int*)xv;
    const long long* x64 = (const long long*)xv;
    const uint4*     tab4 = (const uint4*)s_tab;

    int pre0 = NROWS - 1, pre1 = NROWS - 1;
    if (s_begin < s_end) {
        #pragma unroll
        for (int k = 0; k < 2; k++) {
            int j = tid + k * K1T;
            int samp = s_begin + (j >> 5);
            int v = NROWS - 1;
            if (samp < B) {
                int r = j & 31;
                v = is64 ? (int)x64[(size_t)samp * 32 + r]
                         : x32[samp * 32 + r];
            }
            if (k == 0) pre0 = v; else pre1 = v;
        }
    }

    int buf = 0;
    for (int t0 = s_begin; t0 < s_end; t0 += TILE) {
        s_idx[buf * 1024 + tid]       = pre0;
        s_idx[buf * 1024 + tid + K1T] = pre1;
        __syncthreads();

        int tn = t0 + TILE;
        if (tn < s_end) {
            #pragma unroll
            for (int k = 0; k < 2; k++) {
                int j = tid + k * K1T;
                int samp = tn + (j >> 5);
                int v = NROWS - 1;
                if (samp < B) {
                    int r = j & 31;
                    v = is64 ? (int)x64[(size_t)samp * 32 + r]
                             : x32[samp * 32 + r];
                }
                if (k == 0) pre0 = v; else pre1 = v;
            }
        }

        const int* idx = &s_idx[buf * 1024 + s * 32];

        unsigned long long a0 = 0ull, a1 = 0ull, a2 = 0ull, a3 = 0ull;
        #pragma unroll
        for (int r0 = 0; r0 < 32; r0 += 8) {
            int id[8];
            #pragma unroll
            for (int k = 0; k < 8; k++) id[k] = idx[r0 + k];
            uint4 v[8];
            #pragma unroll
            for (int k = 0; k < 8; k++) v[k] = tab4[id[k] * 16 + q];
            #pragma unroll
            for (int p = 0; p < 4; p++) {
                const uint4& va = v[2 * p];
                const uint4& vb = v[2 * p + 1];
                __half2 hx = __hadd2(*(const __half2*)&va.x, *(const __half2*)&vb.x);
                __half2 hy = __hadd2(*(const __half2*)&va.y, *(const __half2*)&vb.y);
                __half2 hz = __hadd2(*(const __half2*)&va.z, *(const __half2*)&vb.z);
                __half2 hw = __hadd2(*(const __half2*)&va.w, *(const __half2*)&vb.w);
                F2U f0, f1, f2, f3;
                f0.f = __half22float2(hx);
                f1.f = __half22float2(hy);
                f2.f = __half22float2(hz);
                f3.f = __half22float2(hw);
                add2(a0, f0.u);
                add2(a1, f1.u);
                add2(a2, f2.u);
                add2(a3, f3.u);
            }
        }

        int samp = t0 + s;
        if (samp < B) {
            float h[8];
            F2U u0, u1, u2, u3;
            u0.u = a0; u1.u = a1; u2.u = a2; u3.u = a3;
            h[0] = u0.f.x; h[1] = u0.f.y; h[2] = u1.f.x; h[3] = u1.f.y;
            h[4] = u2.f.x; h[5] = u2.f.y; h[6] = u3.f.x; h[7] = u3.f.y;
            const float4 b0 = ((const float4*)s_bias)[2 * q];
            const float4 b1 = ((const float4*)s_bias)[2 * q + 1];
            h[0] = screlu1(h[0] + b0.x); h[1] = screlu1(h[1] + b0.y);
            h[2] = screlu1(h[2] + b0.z); h[3] = screlu1(h[3] + b0.w);
            h[4] = screlu1(h[4] + b1.x); h[5] = screlu1(h[5] + b1.y);
            h[6] = screlu1(h[6] + b1.z); h[7] = screlu1(h[7] + b1.w);

            __half2 o[4];
            #pragma unroll
            for (int k = 0; k < 4; k++)
                o[k] = __floats2half2_rn(h[2 * k], h[2 * k + 1]);
            *(uint4*)(g_hh + ((size_t)samp << 10) + cbase + 8 * q) = *(uint4*)o;
        }
        buf ^= 1;
    }
}

// ---------------------------------------------------------------------------
// K2: warp-level HMMA GEMM + screlu + bucketed heads.
// 128 samples/block, 8 warps; warp w owns samples 16w..16w+15, all 32 j.
// w fp16 staged once (row stride 1032 halves, bank-clean); h chunks (row
// stride 72 halves) triple-buffered (wait_group 1, one barrier per chunk).
// ---------------------------------------------------------------------------
#define W_STRIDE_H 1032                          // halves; 2064 B rows
#define OFF_W    0
#define W_BYTES  (32 * W_STRIDE_H * 2)           // 66048
#define OFF_H    66048
#define HBUF     (128 * 72 * 2)                  // 18432
#define OFF_CPW  (OFF_H + 3 * HBUF)              // 121344
#define OFF_WDLW (OFF_CPW + 1024)                // 122368
#define OFF_FB   (OFF_WDLW + 3072)               // 125440
#define OFF_CB   (OFF_FB + 128)                  // 125568
#define OFF_WB   (OFF_CB + 32)                   // 125600
#define OFF_NZ   (OFF_WB + 96)                   // 125696
#define K2_SMEM  (OFF_NZ + 16)                   // 125712

__global__ __launch_bounds__(K2T)
void mma_fc_kernel(const void* __restrict__ xv,
                   const float* __restrict__ fc2_b,
                   const float* __restrict__ cp_w,  const float* __restrict__ cp_b,
                   const float* __restrict__ wdl_w, const float* __restrict__ wdl_b,
                   const void* __restrict__ pcv,
                   float* __restrict__ out, int B)
{
    extern __shared__ char smem[];
    const uint32_t sbase = smem_u32(smem);

    float* s_cp_w  = (float*)(smem + OFF_CPW);
    float* s_wdl_w = (float*)(smem + OFF_WDLW);
    float* s_fc2_b = (float*)(smem + OFF_FB);
    float* s_cp_b  = (float*)(smem + OFF_CB);
    float* s_wdl_b = (float*)(smem + OFF_WB);
    int*   s_nz    = (int*)(smem + OFF_NZ);

    const int tid = threadIdx.x;
    const int s0  = blockIdx.x * MT;

    if (tid == 0) *s_nz = 0;
    __syncthreads();
    if (tid < 64) {
        if (((const unsigned int*)xv)[2 * tid + 1]) atomicOr(s_nz, 1);
    }
    for (int i = tid; i < 8 * 32; i += K2T)  s_cp_w[i]  = cp_w[i];
    for (int i = tid; i < 24 * 32; i += K2T) s_wdl_w[i] = wdl_w[i];
    if (tid < 32) s_fc2_b[tid] = fc2_b[tid];
    if (tid < 8)  s_cp_b[tid]  = cp_b[tid];
    if (tid < 24) s_wdl_b[tid] = wdl_b[tid];

    // ---- stage all of w fp16 (4096 cp16) + h chunk 0 -> group 0 ----
    #pragma unroll
    for (int r = 0; r < 16; r++) {
        int u   = tid + r * K2T;          // 0..4095
        int j   = u >> 7;                 // 0..31
        int c16 = u & 127;                // 16B units along c
        cp_async16(sbase + OFF_W + (uint32_t)(j * 2064 + c16 * 16),
                   g_w_h + j * HIDDEN + c16 * 8);
    }
    auto stage_h = [&](int k) {
        int buf = k % 3;
        int c0  = k * CK;
        uint32_t hdst = sbase + OFF_H + buf * HBUF;
        #pragma unroll
        for (int r = 0; r < 4; r++) {
            int u   = tid + r * K2T;      // 0..1023
            int p   = u >> 3;             // sample row 0..127
            int u16 = u & 7;
            cp_async16(hdst + (uint32_t)(p * 144 + u16 * 16),
                       g_hh + ((size_t)(s0 + p) << 10) + c0 + u16 * 8);
        }
    };
    stage_h(0);
    CP_COMMIT();                          // G0 = {w, h0}
    stage_h(1);
    CP_COMMIT();                          // G1 = {h1}

    const int l    = tid & 31;
    const int wid5 = tid >> 5;

    // ldmatrix address components
    const uint32_t a_off = (uint32_t)((16 * wid5 + (l & 15)) * 144 + (l >> 4) * 16);
    const uint32_t b_off = (uint32_t)((l & 7) * 2064 + ((l >> 3) & 1) * 16);

    float d[4][4];
    #pragma unroll
    for (int nt = 0; nt < 4; nt++)
        #pragma unroll
        for (int i = 0; i < 4; i++) d[nt][i] = 0.f;

    for (int k = 0; k < NCH; k++) {
        if (k == NCH - 1) { CP_WAIT0(); } else { CP_WAIT1(); }
        __syncthreads();
        if (k + 2 < NCH) { stage_h(k + 2); CP_COMMIT(); }

        const uint32_t habase = sbase + OFF_H + (uint32_t)((k % 3) * HBUF) + a_off;
        const uint32_t wbase  = sbase + OFF_W + b_off + (uint32_t)(k * CK * 2);

        #pragma unroll
        for (int kk = 0; kk < 4; kk++) {
            uint32_t a0, a1, a2, a3;
            asm volatile(
                "ldmatrix.sync.aligned.m8n8.x4.shared.b16 {%0,%1,%2,%3}, [%4];"
                : "=r"(a0), "=r"(a1), "=r"(a2), "=r"(a3)
                : "r"(habase + (uint32_t)(kk * 32)));

            #pragma unroll
            for (int nt = 0; nt < 4; nt++) {
                uint32_t b0, b1;
                asm volatile(
                    "ldmatrix.sync.aligned.m8n8.x2.shared.b16 {%0,%1}, [%2];"
                    : "=r"(b0), "=r"(b1)
                    : "r"(wbase + (uint32_t)(nt * 8 * 2064 + kk * 32)));
                asm volatile(
                    "mma.sync.aligned.m16n8k16.row.col.f32.f16.f16.f32 "
                    "{%0,%1,%2,%3}, {%4,%5,%6,%7}, {%8,%9}, {%0,%1,%2,%3};"
                    : "+f"(d[nt][0]), "+f"(d[nt][1]),
                      "+f"(d[nt][2]), "+f"(d[nt][3])
                    : "r"(a0), "r"(a1), "r"(a2), "r"(a3), "r"(b0), "r"(b1));
            }
        }
    }

    // ---- h2 = screlu(D + b) into smem (reuse hbuf[0]: 128*33*4 <= HBUF) ----
    __syncthreads();
    float* s_h2 = (float*)(smem + OFF_H);
    {
        const int g   = l >> 2;
        const int tig = l & 3;
        const int r0  = 16 * wid5 + g;
        const int r1  = r0 + 8;
        #pragma unroll
        for (int nt = 0; nt < 4; nt++) {
            int j0 = 8 * nt + 2 * tig;
            int j1 = j0 + 1;
            s_h2[r0 * 33 + j0] = screlu1(d[nt][0] + s_fc2_b[j0]);
            s_h2[r0 * 33 + j1] = screlu1(d[nt][1] + s_fc2_b[j1]);
            s_h2[r1 * 33 + j0] = screlu1(d[nt][2] + s_fc2_b[j0]);
            s_h2[r1 * 33 + j1] = screlu1(d[nt][3] + s_fc2_b[j1]);
        }
    }
    __syncthreads();

    // ---- heads: one thread per sample ----
    if (tid < MT) {
        int samp = s0 + tid;
        if (samp < B) {
            const int is64 = (*s_nz == 0);
            int pc = is64 ? (int)((const long long*)pcv)[samp]
                          : ((const int*)pcv)[samp];
            int bkt = (pc - 2) * 8 / 30;
            bkt = max(0, min(7, bkt));

            const float* h2 = &s_h2[tid * 33];
            float cp = s_cp_b[bkt];
            float w0 = s_wdl_b[bkt * 3 + 0];
            float w1 = s_wdl_b[bkt * 3 + 1];
            float w2 = s_wdl_b[bkt * 3 + 2];
            const float* cw  = &s_cp_w[bkt * 32];
            const float* ww0 = &s_wdl_w[(bkt * 3 + 0) * 32];
            const float* ww1 = &s_wdl_w[(bkt * 3 + 1) * 32];
            const float* ww2 = &s_wdl_w[(bkt * 3 + 2) * 32];
            #pragma unroll
            for (int j = 0; j < 32; j++) {
                float hh = h2[j];
                cp = fmaf(hh, cw[j],  cp);
                w0 = fmaf(hh, ww0[j], w0);
                w1 = fmaf(hh, ww1[j], w1);
                w2 = fmaf(hh, ww2[j], w2);
            }
            out[samp] = cp;
            out[B + samp * 3 + 0] = w0;
            out[B + samp * 3 + 1] = w1;
            out[B + samp * 3 + 2] = w2;
        }
    }
}

// ---------------------------------------------------------------------------
extern "C" void kernel_launch(void* const* d_in, const int* in_sizes, int n_in,
                              void* d_out, int out_size)
{
    const void*  x      = d_in[0];
    const void*  pc     = d_in[1];
    const float* emb    = (const float*)d_in[2];
    const float* bias1  = (const float*)d_in[3];
    const float* fc2_w  = (const float*)d_in[4];
    const float* fc2_b  = (const float*)d_in[5];
    const float* cp_w   = (const float*)d_in[6];
    const float* cp_b   = (const float*)d_in[7];
    const float* wdl_w  = (const float*)d_in[8];
    const float* wdl_b  = (const float*)d_in[9];

    int B = in_sizes[0] / 32;
    if (B > MAX_B) B = MAX_B;

    prep_kernel<<<NROWS + 32, 512>>>(emb, fc2_w);

    const int k1_smem = NROWS * CHUNK1 * 2 + 8192 + CHUNK1 * 4 + 16;
    cudaFuncSetAttribute(gather_kernel,
                         cudaFuncAttributeMaxDynamicSharedMemorySize, k1_smem);
    dim3 g1(NCHUNKS1, NGROUPS1);
    gather_kernel<<<g1, K1T, k1_smem>>>(x, bias1, B);

    cudaFuncSetAttribute(mma_fc_kernel,
                         cudaFuncAttributeMaxDynamicSharedMemorySize, K2_SMEM);
    int g2 = (B + MT - 1) / MT;
    mma_fc_kernel<<<g2, K2T, K2_SMEM>>>(x, fc2_b, cp_w, cp_b, wdl_w, wdl_b,
                                        pc, (float*)d_out, B);
}